// round 6
// baseline (speedup 1.0000x reference)
#include <cuda_runtime.h>
#include <cuda_bf16.h>
#include <cstdint>
#include <math.h>

// Problem constants
#define B_ 2
#define S_ 1024
#define D_ 1024
#define H_ 16
#define DH_ 64
#define L_ 8
#define FF_ 4096
#define V_ 32000
#define BS_ (B_ * S_)
#define K3D (3 * D_)    // 3072
#define K3F (3 * FF_)   // 12288

// ---------------- scratch (device globals) ----------------
__device__ float g_h[BS_ * D_];
__device__ float g_qkv[BS_ * K3D];
__device__ __nv_bfloat16 g_asmall[BS_ * K3D];  // D-width bf16x3 activations
__device__ __nv_bfloat16 g_abig[BS_ * K3F];    // FF-width bf16x3 activations
__device__ __nv_bfloat16 g_bqkv[(size_t)L_ * K3D * K3D];
__device__ __nv_bfloat16 g_bwo[(size_t)L_ * D_ * K3D];
__device__ __nv_bfloat16 g_bw1[(size_t)L_ * FF_ * K3D];
__device__ __nv_bfloat16 g_bw2[(size_t)L_ * D_ * K3F];
__device__ __nv_bfloat16 g_bwout[(size_t)V_ * K3D];

// ---------------- helpers ----------------
__device__ __forceinline__ uint32_t smem_u32(const void* p) {
    uint32_t a;
    asm("{ .reg .u64 t; cvta.to.shared.u64 t, %1; cvt.u32.u64 %0, t; }" : "=r"(a) : "l"(p));
    return a;
}
__device__ __forceinline__ void cp_async16(uint32_t dst, const void* src) {
    asm volatile("cp.async.cg.shared.global [%0], [%1], 16;" :: "r"(dst), "l"(src) : "memory");
}
__device__ __forceinline__ void cp_commit() {
    asm volatile("cp.async.commit_group;" ::: "memory");
}
template <int N>
__device__ __forceinline__ void cp_wait() {
    asm volatile("cp.async.wait_group %0;" :: "n"(N) : "memory");
}
__device__ __forceinline__ void ldmatrix_x4(uint32_t* r, uint32_t addr) {
    asm volatile("ldmatrix.sync.aligned.m8n8.x4.shared.b16 {%0,%1,%2,%3}, [%4];"
                 : "=r"(r[0]), "=r"(r[1]), "=r"(r[2]), "=r"(r[3]) : "r"(addr));
}
__device__ __forceinline__ void mma16816(float* c, const uint32_t* a, uint32_t b0, uint32_t b1) {
    asm volatile(
        "mma.sync.aligned.m16n8k16.row.col.f32.bf16.bf16.f32 "
        "{%0,%1,%2,%3}, {%4,%5,%6,%7}, {%8,%9}, {%0,%1,%2,%3};"
        : "+f"(c[0]), "+f"(c[1]), "+f"(c[2]), "+f"(c[3])
        : "r"(a[0]), "r"(a[1]), "r"(a[2]), "r"(a[3]), "r"(b0), "r"(b1));
}
__device__ __forceinline__ void split_write(__nv_bfloat16* out, long ro, long seg, int c, float v) {
    __nv_bfloat16 hi = __float2bfloat16(v);
    __nv_bfloat16 lo = __float2bfloat16(v - __bfloat162float(hi));
    out[ro + c] = hi;
    out[ro + seg + c] = hi;
    out[ro + 2 * seg + c] = lo;
}

// ---------------- reductions ----------------
__device__ __forceinline__ float warpReduceSum(float v) {
    #pragma unroll
    for (int o = 16; o > 0; o >>= 1) v += __shfl_xor_sync(0xffffffffu, v, o);
    return v;
}
__device__ __forceinline__ float warpReduceMax(float v) {
    #pragma unroll
    for (int o = 16; o > 0; o >>= 1) v = fmaxf(v, __shfl_xor_sync(0xffffffffu, v, o));
    return v;
}
__device__ float blockReduceSum(float v) {
    __shared__ float sh[33];
    __syncthreads();
    int lane = threadIdx.x & 31, w = threadIdx.x >> 5;
    v = warpReduceSum(v);
    if (lane == 0) sh[w] = v;
    __syncthreads();
    int nw = (blockDim.x + 31) >> 5;
    float r = (threadIdx.x < nw) ? sh[threadIdx.x] : 0.0f;
    if (w == 0) { r = warpReduceSum(r); if (lane == 0) sh[32] = r; }
    __syncthreads();
    return sh[32];
}
__device__ float blockReduceMax(float v) {
    __shared__ float sh[33];
    __syncthreads();
    int lane = threadIdx.x & 31, w = threadIdx.x >> 5;
    v = warpReduceMax(v);
    if (lane == 0) sh[w] = v;
    __syncthreads();
    int nw = (blockDim.x + 31) >> 5;
    float r = (threadIdx.x < nw) ? sh[threadIdx.x] : -3.0e38f;
    if (w == 0) { r = warpReduceMax(r); if (lane == 0) sh[32] = r; }
    __syncthreads();
    return sh[32];
}

// ---------------- weight transpose + bf16x3 split -----------------
__global__ void transpose_split_kernel(const float* __restrict__ W, __nv_bfloat16* __restrict__ out,
                                       int K, int N, long in_z_stride, long out_l_stride,
                                       int h_group, int row_off, int Kp) {
    int z = blockIdx.z;
    int l = z / h_group, h = z % h_group;
    const float* Win = W + (long)z * in_z_stride;
    __nv_bfloat16* O = out + (long)l * out_l_stride;
    int base_row = row_off + h * N;
    __shared__ float t[32][33];
    int kb = blockIdx.y * 32, nb = blockIdx.x * 32;
    #pragma unroll
    for (int j = 0; j < 4; j++) {
        int r = threadIdx.y + j * 8;
        int k = kb + r, n = nb + threadIdx.x;
        t[r][threadIdx.x] = (k < K && n < N) ? Win[(long)k * N + n] : 0.0f;
    }
    __syncthreads();
    #pragma unroll
    for (int j = 0; j < 4; j++) {
        int r = threadIdx.y + j * 8;
        int n = nb + r, k = kb + threadIdx.x;
        if (n < N && k < K) {
            float w = t[threadIdx.x][r];
            __nv_bfloat16 hi = __float2bfloat16(w);
            __nv_bfloat16 lo = __float2bfloat16(w - __bfloat162float(hi));
            long ro = (long)(base_row + n) * Kp;
            O[ro + k] = hi;
            O[ro + K + k] = lo;
            O[ro + 2 * K + k] = hi;
        }
    }
}

// ---------------- mma.sync GEMM: C[M,N] = A[M,K'] * B[N,K']^T ----------------
// BM=64: 256 thr, 8 warps 2x4, 2 CTAs/SM.  BM=128: 512 thr, 16 warps 4x4, 1 CTA/SM.
// Warp tile 32x32 in both. BK=64, 3-stage cp.async pipeline.
// MODE: 0 none, 1 bias, 2 bias+resid, 4 bias+relu+split(Cs)
#define STAGES 3
template <int BM, int MODE>
__global__ __launch_bounds__((BM == 128) ? 512 : 256, (BM == 128) ? 1 : 2)
void mma_gemm_kernel(
    const __nv_bfloat16* __restrict__ A, const __nv_bfloat16* __restrict__ Bw,
    const float* __restrict__ bias, const float* __restrict__ resid,
    float* __restrict__ C, __nv_bfloat16* __restrict__ Cs, int N, int K3) {
    constexpr int THREADS = (BM == 128) ? 512 : 256;
    constexpr int WMN = (BM == 128) ? 4 : 2;
    constexpr int ROWS_PER_IT = THREADS / 8;
    constexpr int AITER = BM / ROWS_PER_IT;
    constexpr int BITER = 128 / ROWS_PER_IT;
    constexpr int ABYTES = BM * 128;
    constexpr int STAGE = ABYTES + 16384;

    extern __shared__ char sm[];
    uint32_t smb = smem_u32(sm);

    int tid = threadIdx.x, lane = tid & 31, wid = tid >> 5;
    int wm = wid % WMN;
    int wn = wid / WMN;
    int row0 = blockIdx.y * BM, col0 = blockIdx.x * 128;

    const char* Ab = (const char*)A;
    const char* Bb = (const char*)Bw;
    long strideB = (long)K3 * 2;

    int nc = K3 >> 6;

    auto load_chunk = [&](int c, int s) {
        long kcb = (long)c * 128;
        uint32_t bA = smb + (uint32_t)s * STAGE;
        uint32_t bB = bA + ABYTES;
        #pragma unroll
        for (int j = 0; j < AITER; j++) {
            int i = tid + j * THREADS;
            int r = i >> 3;
            uint32_t cb = (uint32_t)(i & 7) * 16;
            uint32_t off = (uint32_t)r * 128 + cb;
            uint32_t sw = off ^ ((off >> 3) & 0x70);
            cp_async16(bA + sw, Ab + (long)(row0 + r) * strideB + kcb + cb);
        }
        #pragma unroll
        for (int j = 0; j < BITER; j++) {
            int i = tid + j * THREADS;
            int r = i >> 3;
            uint32_t cb = (uint32_t)(i & 7) * 16;
            uint32_t off = (uint32_t)r * 128 + cb;
            uint32_t sw = off ^ ((off >> 3) & 0x70);
            cp_async16(bB + sw, Bb + (long)(col0 + r) * strideB + kcb + cb);
        }
        cp_commit();
    };

    float acc[2][4][4];
    #pragma unroll
    for (int i = 0; i < 2; i++)
        #pragma unroll
        for (int j = 0; j < 4; j++)
            #pragma unroll
            for (int k = 0; k < 4; k++) acc[i][j][k] = 0.0f;

    #pragma unroll
    for (int s = 0; s < STAGES - 1; s++)
        if (s < nc) load_chunk(s, s);

    for (int c = 0; c < nc; c++) {
        if (c + 1 < nc) cp_wait<STAGES - 2>();
        else cp_wait<0>();
        __syncthreads();
        int nxt = c + STAGES - 1;
        if (nxt < nc) load_chunk(nxt, nxt % STAGES);

        int st = c % STAGES;
        uint32_t bufA = smb + (uint32_t)st * STAGE;
        uint32_t bufB = bufA + ABYTES;

        #pragma unroll
        for (int s = 0; s < 4; s++) {
            int kb = s * 32 + (lane >> 4) * 16;
            uint32_t aF[2][4], bF[2][4];
            #pragma unroll
            for (int fm = 0; fm < 2; fm++) {
                uint32_t off = (uint32_t)(wm * 32 + fm * 16 + (lane & 15)) * 128 + kb;
                ldmatrix_x4(aF[fm], bufA + (off ^ ((off >> 3) & 0x70)));
            }
            #pragma unroll
            for (int fb = 0; fb < 2; fb++) {
                uint32_t off = (uint32_t)(wn * 32 + fb * 16 + (lane & 15)) * 128 + kb;
                ldmatrix_x4(bF[fb], bufB + (off ^ ((off >> 3) & 0x70)));
            }
            #pragma unroll
            for (int fm = 0; fm < 2; fm++)
                #pragma unroll
                for (int fn = 0; fn < 4; fn++) {
                    int fb = fn >> 1, odd = fn & 1;
                    mma16816(acc[fm][fn], aF[fm], bF[fb][odd], bF[fb][odd + 2]);
                }
        }
    }

    // epilogue
    #pragma unroll
    for (int fm = 0; fm < 2; fm++) {
        #pragma unroll
        for (int fn = 0; fn < 4; fn++) {
            int gr = row0 + wm * 32 + fm * 16 + (lane >> 2);
            int gc = col0 + wn * 32 + fn * 8 + 2 * (lane & 3);
            float v0 = acc[fm][fn][0], v1 = acc[fm][fn][1];
            float v2 = acc[fm][fn][2], v3 = acc[fm][fn][3];
            if (MODE >= 1) {
                float b0 = bias[gc], b1 = bias[gc + 1];
                v0 += b0; v1 += b1; v2 += b0; v3 += b1;
            }
            if (MODE == 2) {
                v0 += resid[(long)gr * N + gc];
                v1 += resid[(long)gr * N + gc + 1];
                v2 += resid[(long)(gr + 8) * N + gc];
                v3 += resid[(long)(gr + 8) * N + gc + 1];
            }
            if (MODE == 4) {
                v0 = fmaxf(v0, 0.0f); v1 = fmaxf(v1, 0.0f);
                v2 = fmaxf(v2, 0.0f); v3 = fmaxf(v3, 0.0f);
                long ro0 = (long)gr * (3L * N), ro8 = (long)(gr + 8) * (3L * N);
                split_write(Cs, ro0, N, gc, v0);
                split_write(Cs, ro0, N, gc + 1, v1);
                split_write(Cs, ro8, N, gc, v2);
                split_write(Cs, ro8, N, gc + 1, v3);
            } else {
                *(float2*)&C[(long)gr * N + gc] = make_float2(v0, v1);
                *(float2*)&C[(long)(gr + 8) * N + gc] = make_float2(v2, v3);
            }
        }
    }
}

#define SMEM_BM128 (STAGES * (128 * 128 + 16384))
#define SMEM_BM64  (STAGES * (64 * 128 + 16384))

static void run_tc64(const __nv_bfloat16* A, const __nv_bfloat16* B, const float* bias,
                     const float* resid, float* C, int N, int K3, int mode) {
    dim3 grid(N / 128, BS_ / 64);
    if (mode == 0) mma_gemm_kernel<64, 0><<<grid, 256, SMEM_BM64>>>(A, B, bias, resid, C, nullptr, N, K3);
    else           mma_gemm_kernel<64, 2><<<grid, 256, SMEM_BM64>>>(A, B, bias, resid, C, nullptr, N, K3);
}
static void run_tc128_bias(const __nv_bfloat16* A, const __nv_bfloat16* B, const float* bias,
                           float* C, int N, int K3) {
    dim3 grid(N / 128, BS_ / 128);
    mma_gemm_kernel<128, 1><<<grid, 512, SMEM_BM128>>>(A, B, bias, nullptr, C, nullptr, N, K3);
}
static void run_tc128_relu_split(const __nv_bfloat16* A, const __nv_bfloat16* B, const float* bias,
                                 __nv_bfloat16* Cs, int N, int K3) {
    dim3 grid(N / 128, BS_ / 128);
    mma_gemm_kernel<128, 4><<<grid, 512, SMEM_BM128>>>(A, B, bias, nullptr, nullptr, Cs, N, K3);
}

// ---------------- embedding ----------------
__global__ void embed_kernel(const int* __restrict__ tokens,
                             const float* __restrict__ tok_emb,
                             const float* __restrict__ pos_emb,
                             float* __restrict__ h) {
    int i = blockIdx.x * blockDim.x + threadIdx.x;
    if (i >= BS_ * D_) return;
    int d = i % D_;
    int bs = i / D_;
    int s = bs % S_;
    int tok = tokens[bs];
    h[i] = tok_emb[(size_t)tok * D_ + d] + pos_emb[(size_t)s * D_ + d];
}

// ---------------- layernorm fused with bf16x3 split ----------------
__global__ void layernorm_split_kernel(const float* __restrict__ x,
                                       const float* __restrict__ g,
                                       const float* __restrict__ b,
                                       __nv_bfloat16* __restrict__ out) {
    int row = blockIdx.x;
    const float* xr = x + (size_t)row * D_;
    float vals[4];
    float s = 0.0f;
    #pragma unroll
    for (int j = 0; j < 4; j++) { vals[j] = xr[threadIdx.x + j * 256]; s += vals[j]; }
    float mean = blockReduceSum(s) * (1.0f / D_);
    float var = 0.0f;
    #pragma unroll
    for (int j = 0; j < 4; j++) { float d = vals[j] - mean; var += d * d; }
    var = blockReduceSum(var) * (1.0f / D_);
    float rstd = rsqrtf(var + 1e-5f);
    long ro = (long)row * K3D;
    #pragma unroll
    for (int j = 0; j < 4; j++) {
        int i = threadIdx.x + j * 256;
        float v = (vals[j] - mean) * rstd * g[i] + b[i];
        split_write(out, ro, D_, i, v);
    }
}

// ---------------- flash-tiled causal attention (split output) --------------
#define QT 64
#define ROWP 68
__global__ __launch_bounds__(256) void flash_attn_kernel(const float* __restrict__ QKV,
                                                         __nv_bfloat16* __restrict__ Osplit) {
    extern __shared__ float fsm[];
    float* sQ = fsm;
    float* sK = fsm + 64 * ROWP;
    float* sV = fsm + 2 * 64 * ROWP;
    float* sP = fsm + 3 * 64 * ROWP;

    int qt = blockIdx.x, h = blockIdx.y, b = blockIdx.z;
    int q0 = qt * QT;
    int tid = threadIdx.x;
    int r = tid >> 2, c4 = tid & 3;
    const float scale = 0.03125f;  // D^-0.5 (reference scales by embedding dim)

    #pragma unroll
    for (int i = 0; i < 4; i++) {
        int lin = tid + i * 256;
        int rr = lin >> 4, cc = (lin & 15) * 4;
        float4 v = *(const float4*)&QKV[((size_t)(b * S_ + q0 + rr)) * K3D + h * DH_ + cc];
        *(float4*)&sQ[rr * ROWP + cc] = v;
    }

    float m_run = -1.0e30f, l_run = 0.0f;
    float acc[16];
    #pragma unroll
    for (int i = 0; i < 16; i++) acc[i] = 0.0f;

    for (int jt = 0; jt <= qt; jt++) {
        __syncthreads();
        int k0 = jt * QT;
        #pragma unroll
        for (int i = 0; i < 4; i++) {
            int lin = tid + i * 256;
            int rr = lin >> 4, cc = (lin & 15) * 4;
            size_t base = ((size_t)(b * S_ + k0 + rr)) * K3D + h * DH_ + cc;
            *(float4*)&sK[rr * ROWP + cc] = *(const float4*)&QKV[base + D_];
            *(float4*)&sV[rr * ROWP + cc] = *(const float4*)&QKV[base + 2 * D_];
        }
        __syncthreads();

        float sc[16];
        float tmax = -1.0e30f;
        bool diag = (jt == qt);
        #pragma unroll
        for (int kk = 0; kk < 16; kk++) {
            int kl = kk * 4 + c4;
            float s = 0.0f;
            const float* qr = &sQ[r * ROWP];
            const float* kr = &sK[kl * ROWP];
            #pragma unroll
            for (int e = 0; e < DH_; e++) s = fmaf(qr[e], kr[e], s);
            s *= scale;
            if (diag && kl > r) s = -1.0e30f;
            sc[kk] = s;
            tmax = fmaxf(tmax, s);
        }
        tmax = fmaxf(tmax, __shfl_xor_sync(0xffffffffu, tmax, 1));
        tmax = fmaxf(tmax, __shfl_xor_sync(0xffffffffu, tmax, 2));
        float m_new = fmaxf(m_run, tmax);
        float f = __expf(m_run - m_new);
        float sp = 0.0f;
        #pragma unroll
        for (int kk = 0; kk < 16; kk++) {
            float p = __expf(sc[kk] - m_new);
            sP[r * ROWP + kk * 4 + c4] = p;
            sp += p;
        }
        sp += __shfl_xor_sync(0xffffffffu, sp, 1);
        sp += __shfl_xor_sync(0xffffffffu, sp, 2);
        l_run = l_run * f + sp;
        m_run = m_new;
        #pragma unroll
        for (int i = 0; i < 16; i++) acc[i] *= f;
        __syncwarp();

        const float* pr = &sP[r * ROWP];
        #pragma unroll 8
        for (int kk = 0; kk < 64; kk++) {
            float p = pr[kk];
            const float* vr = &sV[kk * ROWP + c4 * 16];
            #pragma unroll
            for (int d = 0; d < 16; d++) acc[d] = fmaf(p, vr[d], acc[d]);
        }
    }

    float inv = 1.0f / l_run;
    long m = (long)(b * S_ + q0 + r);
    long ro = m * K3D;
    int dbase = h * DH_ + c4 * 16;
    #pragma unroll
    for (int d = 0; d < 16; d++)
        split_write(Osplit, ro, D_, dbase + d, acc[d] * inv);
}
#define ATTN_SMEM (4 * 64 * ROWP * 4)

// ---------------- loss ----------------
__global__ void zero_kernel(float* p) { *p = 0.0f; }

__global__ void loss_kernel(const float* __restrict__ logits,
                            const int* __restrict__ targets,
                            float* __restrict__ loss, float invN) {
    int row = blockIdx.x;
    const float* lr = logits + (size_t)row * V_;
    float lmax = -3.0e38f;
    for (int i = threadIdx.x; i < V_; i += blockDim.x) lmax = fmaxf(lmax, lr[i]);
    float m = blockReduceMax(lmax);
    float lsum = 0.0f;
    for (int i = threadIdx.x; i < V_; i += blockDim.x) lsum += __expf(lr[i] - m);
    float s = blockReduceSum(lsum);
    if (threadIdx.x == 0) {
        float lse = m + logf(s);
        float nll = lse - lr[targets[row]];
        atomicAdd(loss, nll * invN);
    }
}

// ---------------- launch ----------------
extern "C" void kernel_launch(void* const* d_in, const int* in_sizes, int n_in,
                              void* d_out, int out_size) {
    const int* tokens = (const int*)d_in[0];
    const int* targets = (const int*)d_in[1];
    const float* tok_emb = (const float*)d_in[2];
    const float* pos_emb = (const float*)d_in[3];
    const float* Wq = (const float*)d_in[4];
    const float* Wk = (const float*)d_in[5];
    const float* Wv = (const float*)d_in[6];
    const float* Wo = (const float*)d_in[7];
    const float* bo = (const float*)d_in[8];
    const float* ln1_g = (const float*)d_in[9];
    const float* ln1_b = (const float*)d_in[10];
    const float* ln2_g = (const float*)d_in[11];
    const float* ln2_b = (const float*)d_in[12];
    const float* W1 = (const float*)d_in[13];
    const float* b1 = (const float*)d_in[14];
    const float* W2 = (const float*)d_in[15];
    const float* b2 = (const float*)d_in[16];
    const float* lnf_g = (const float*)d_in[17];
    const float* lnf_b = (const float*)d_in[18];
    const float* Wout = (const float*)d_in[19];
    const float* bout = (const float*)d_in[20];
    float* out = (float*)d_out;

    cudaFuncSetAttribute((const void*)mma_gemm_kernel<64, 0>, cudaFuncAttributeMaxDynamicSharedMemorySize, SMEM_BM64);
    cudaFuncSetAttribute((const void*)mma_gemm_kernel<64, 2>, cudaFuncAttributeMaxDynamicSharedMemorySize, SMEM_BM64);
    cudaFuncSetAttribute((const void*)mma_gemm_kernel<128, 1>, cudaFuncAttributeMaxDynamicSharedMemorySize, SMEM_BM128);
    cudaFuncSetAttribute((const void*)mma_gemm_kernel<128, 4>, cudaFuncAttributeMaxDynamicSharedMemorySize, SMEM_BM128);
    cudaFuncSetAttribute((const void*)flash_attn_kernel, cudaFuncAttributeMaxDynamicSharedMemorySize, ATTN_SMEM);

    float *h, *qkv;
    __nv_bfloat16 *asmall, *abig, *bqkv, *bwo, *bw1, *bw2, *bwout;
    cudaGetSymbolAddress((void**)&h, g_h);
    cudaGetSymbolAddress((void**)&qkv, g_qkv);
    cudaGetSymbolAddress((void**)&asmall, g_asmall);
    cudaGetSymbolAddress((void**)&abig, g_abig);
    cudaGetSymbolAddress((void**)&bqkv, g_bqkv);
    cudaGetSymbolAddress((void**)&bwo, g_bwo);
    cudaGetSymbolAddress((void**)&bw1, g_bw1);
    cudaGetSymbolAddress((void**)&bw2, g_bw2);
    cudaGetSymbolAddress((void**)&bwout, g_bwout);

    // ---- weight prep ----
    dim3 tb(32, 8);
    transpose_split_kernel<<<dim3(2, 32, L_ * H_), tb>>>(Wq, bqkv, D_, DH_, (long)D_ * DH_, (long)K3D * K3D, H_, 0, K3D);
    transpose_split_kernel<<<dim3(2, 32, L_ * H_), tb>>>(Wk, bqkv, D_, DH_, (long)D_ * DH_, (long)K3D * K3D, H_, D_, K3D);
    transpose_split_kernel<<<dim3(2, 32, L_ * H_), tb>>>(Wv, bqkv, D_, DH_, (long)D_ * DH_, (long)K3D * K3D, H_, 2 * D_, K3D);
    transpose_split_kernel<<<dim3(32, 32, L_), tb>>>(Wo, bwo, D_, D_, (long)D_ * D_, (long)D_ * K3D, 1, 0, K3D);
    transpose_split_kernel<<<dim3(128, 32, L_), tb>>>(W1, bw1, D_, FF_, (long)D_ * FF_, (long)FF_ * K3D, 1, 0, K3D);
    transpose_split_kernel<<<dim3(32, 128, L_), tb>>>(W2, bw2, FF_, D_, (long)FF_ * D_, (long)D_ * K3F, 1, 0, K3F);
    transpose_split_kernel<<<dim3(1000, 32, 1), tb>>>(Wout, bwout, D_, V_, 0, 0, 1, 0, K3D);

    embed_kernel<<<(BS_ * D_ + 255) / 256, 256>>>(tokens, tok_emb, pos_emb, h);

    for (int l = 0; l < L_; l++) {
        layernorm_split_kernel<<<BS_, 256>>>(h, ln1_g + (size_t)l * D_, ln1_b + (size_t)l * D_, asmall);
        run_tc64(asmall, bqkv + (size_t)l * K3D * K3D, nullptr, nullptr, qkv, K3D, K3D, 0);
        dim3 ag(S_ / QT, H_, B_);
        flash_attn_kernel<<<ag, 256, ATTN_SMEM>>>(qkv, asmall);
        run_tc64(asmall, bwo + (size_t)l * D_ * K3D, bo + (size_t)l * D_, h, h, D_, K3D, 2);
        layernorm_split_kernel<<<BS_, 256>>>(h, ln2_g + (size_t)l * D_, ln2_b + (size_t)l * D_, asmall);
        run_tc128_relu_split(asmall, bw1 + (size_t)l * FF_ * K3D, b1 + (size_t)l * FF_, abig, FF_, K3D);
        run_tc64(abig, bw2 + (size_t)l * D_ * K3F, b2 + (size_t)l * D_, h, h, D_, K3F, 2);
    }

    layernorm_split_kernel<<<BS_, 256>>>(h, lnf_g, lnf_b, asmall);
    run_tc128_bias(asmall, bwout, bout, out, V_, K3D);

    long long BSV = (long long)BS_ * V_;
    if ((long long)out_size > BSV) {
        zero_kernel<<<1, 1>>>(out + BSV);
        loss_kernel<<<BS_, 256>>>(out, targets, out + BSV, 1.0f / BS_);
    }
}

// round 8
// speedup vs baseline: 1.0527x; 1.0527x over previous
#include <cuda_runtime.h>
#include <cuda_bf16.h>
#include <cstdint>
#include <math.h>

// Problem constants
#define B_ 2
#define S_ 1024
#define D_ 1024
#define H_ 16
#define DH_ 64
#define L_ 8
#define FF_ 4096
#define V_ 32000
#define BS_ (B_ * S_)
#define K3D (3 * D_)    // 3072
#define K3F (3 * FF_)   // 12288

// ---------------- scratch (device globals) ----------------
__device__ float g_h[BS_ * D_];
__device__ float g_xn[BS_ * D_];
__device__ float g_qkv[BS_ * K3D];
__device__ float g_o[BS_ * D_];
__device__ float g_ff[BS_ * FF_];
__device__ __nv_bfloat16 g_abig[BS_ * K3F];
__device__ __nv_bfloat16 g_bqkv[(size_t)L_ * K3D * K3D];
__device__ __nv_bfloat16 g_bwo[(size_t)L_ * D_ * K3D];
__device__ __nv_bfloat16 g_bw1[(size_t)L_ * FF_ * K3D];
__device__ __nv_bfloat16 g_bw2[(size_t)L_ * D_ * K3F];
__device__ __nv_bfloat16 g_bwout[(size_t)V_ * K3D];

// ---------------- helpers ----------------
__device__ __forceinline__ uint32_t smem_u32(const void* p) {
    uint32_t a;
    asm("{ .reg .u64 t; cvta.to.shared.u64 t, %1; cvt.u32.u64 %0, t; }" : "=r"(a) : "l"(p));
    return a;
}
__device__ __forceinline__ void cp_async16(uint32_t dst, const void* src) {
    asm volatile("cp.async.cg.shared.global [%0], [%1], 16;" :: "r"(dst), "l"(src) : "memory");
}
__device__ __forceinline__ void cp_commit() {
    asm volatile("cp.async.commit_group;" ::: "memory");
}
template <int N>
__device__ __forceinline__ void cp_wait() {
    asm volatile("cp.async.wait_group %0;" :: "n"(N) : "memory");
}
__device__ __forceinline__ void ldmatrix_x4(uint32_t* r, uint32_t addr) {
    asm volatile("ldmatrix.sync.aligned.m8n8.x4.shared.b16 {%0,%1,%2,%3}, [%4];"
                 : "=r"(r[0]), "=r"(r[1]), "=r"(r[2]), "=r"(r[3]) : "r"(addr));
}
__device__ __forceinline__ void mma16816(float* c, const uint32_t* a, uint32_t b0, uint32_t b1) {
    asm volatile(
        "mma.sync.aligned.m16n8k16.row.col.f32.bf16.bf16.f32 "
        "{%0,%1,%2,%3}, {%4,%5,%6,%7}, {%8,%9}, {%0,%1,%2,%3};"
        : "+f"(c[0]), "+f"(c[1]), "+f"(c[2]), "+f"(c[3])
        : "r"(a[0]), "r"(a[1]), "r"(a[2]), "r"(a[3]), "r"(b0), "r"(b1));
}

// ---------------- reductions ----------------
__device__ __forceinline__ float warpReduceSum(float v) {
    #pragma unroll
    for (int o = 16; o > 0; o >>= 1) v += __shfl_xor_sync(0xffffffffu, v, o);
    return v;
}
__device__ __forceinline__ float warpReduceMax(float v) {
    #pragma unroll
    for (int o = 16; o > 0; o >>= 1) v = fmaxf(v, __shfl_xor_sync(0xffffffffu, v, o));
    return v;
}
__device__ float blockReduceSum(float v) {
    __shared__ float sh[33];
    __syncthreads();
    int lane = threadIdx.x & 31, w = threadIdx.x >> 5;
    v = warpReduceSum(v);
    if (lane == 0) sh[w] = v;
    __syncthreads();
    int nw = (blockDim.x + 31) >> 5;
    float r = (threadIdx.x < nw) ? sh[threadIdx.x] : 0.0f;
    if (w == 0) { r = warpReduceSum(r); if (lane == 0) sh[32] = r; }
    __syncthreads();
    return sh[32];
}
__device__ float blockReduceMax(float v) {
    __shared__ float sh[33];
    __syncthreads();
    int lane = threadIdx.x & 31, w = threadIdx.x >> 5;
    v = warpReduceMax(v);
    if (lane == 0) sh[w] = v;
    __syncthreads();
    int nw = (blockDim.x + 31) >> 5;
    float r = (threadIdx.x < nw) ? sh[threadIdx.x] : -3.0e38f;
    if (w == 0) { r = warpReduceMax(r); if (lane == 0) sh[32] = r; }
    __syncthreads();
    return sh[32];
}

// ---------------- weight transpose + bf16x3 split -----------------
__global__ void transpose_split_kernel(const float* __restrict__ W, __nv_bfloat16* __restrict__ out,
                                       int K, int N, long in_z_stride, long out_l_stride,
                                       int h_group, int row_off, int Kp) {
    int z = blockIdx.z;
    int l = z / h_group, h = z % h_group;
    const float* Win = W + (long)z * in_z_stride;
    __nv_bfloat16* O = out + (long)l * out_l_stride;
    int base_row = row_off + h * N;
    __shared__ float t[32][33];
    int kb = blockIdx.y * 32, nb = blockIdx.x * 32;
    #pragma unroll
    for (int j = 0; j < 4; j++) {
        int r = threadIdx.y + j * 8;
        int k = kb + r, n = nb + threadIdx.x;
        t[r][threadIdx.x] = (k < K && n < N) ? Win[(long)k * N + n] : 0.0f;
    }
    __syncthreads();
    #pragma unroll
    for (int j = 0; j < 4; j++) {
        int r = threadIdx.y + j * 8;
        int n = nb + r, k = kb + threadIdx.x;
        if (n < N && k < K) {
            float w = t[threadIdx.x][r];
            __nv_bfloat16 hi = __float2bfloat16(w);
            __nv_bfloat16 lo = __float2bfloat16(w - __bfloat162float(hi));
            long ro = (long)(base_row + n) * Kp;
            O[ro + k] = hi;
            O[ro + K + k] = lo;
            O[ro + 2 * K + k] = hi;
        }
    }
}

// Activation split: A[M,K] fp32 -> [hi | hi | lo] bf16 [M, 3K]
__global__ void act_split_kernel(const float* __restrict__ A, __nv_bfloat16* __restrict__ out, int K) {
    long i = (long)blockIdx.x * 256 + threadIdx.x;
    int k = (int)(i % K);
    long m = i / K;
    float w = A[i];
    __nv_bfloat16 hi = __float2bfloat16(w);
    __nv_bfloat16 lo = __float2bfloat16(w - __bfloat162float(hi));
    long ro = m * (long)(3 * K);
    out[ro + k] = hi;
    out[ro + K + k] = hi;
    out[ro + 2 * K + k] = lo;
}

// ---------------- mma.sync GEMM: C[M,N] = A[M,K'] * B[N,K']^T ----------------
// BM=64 only: 256 thr, 8 warps 2(M)x4(N), warp tile 32x32, 2 CTAs/SM.
// BK=64, 3-stage cp.async pipeline.
// MODE: 0 none, 1 bias, 2 bias+resid, 3 bias+relu
#define STAGES 3
#define SMEM_BM64 (STAGES * (64 * 128 + 16384))
template <int MODE>
__global__ __launch_bounds__(256, 2) void mma_gemm_kernel(
    const __nv_bfloat16* __restrict__ A, const __nv_bfloat16* __restrict__ Bw,
    const float* __restrict__ bias, const float* __restrict__ resid,
    float* __restrict__ C, int N, int K3) {
    constexpr int ABYTES = 64 * 128;
    constexpr int STAGE = ABYTES + 16384;

    extern __shared__ char sm[];
    uint32_t smb = smem_u32(sm);

    int tid = threadIdx.x, lane = tid & 31, wid = tid >> 5;
    int wm = wid & 1;          // 2 warps along M
    int wn = wid >> 1;         // 4 warps along N
    int row0 = blockIdx.y * 64, col0 = blockIdx.x * 128;

    const char* Ab = (const char*)A;
    const char* Bb = (const char*)Bw;
    long strideB = (long)K3 * 2;

    int nc = K3 >> 6;

    auto load_chunk = [&](int c, int s) {
        long kcb = (long)c * 128;
        uint32_t bA = smb + (uint32_t)s * STAGE;
        uint32_t bB = bA + ABYTES;
        #pragma unroll
        for (int j = 0; j < 2; j++) {
            int i = tid + j * 256;
            int r = i >> 3;
            uint32_t cb = (uint32_t)(i & 7) * 16;
            uint32_t off = (uint32_t)r * 128 + cb;
            uint32_t sw = off ^ ((off >> 3) & 0x70);
            cp_async16(bA + sw, Ab + (long)(row0 + r) * strideB + kcb + cb);
        }
        #pragma unroll
        for (int j = 0; j < 4; j++) {
            int i = tid + j * 256;
            int r = i >> 3;
            uint32_t cb = (uint32_t)(i & 7) * 16;
            uint32_t off = (uint32_t)r * 128 + cb;
            uint32_t sw = off ^ ((off >> 3) & 0x70);
            cp_async16(bB + sw, Bb + (long)(col0 + r) * strideB + kcb + cb);
        }
        cp_commit();
    };

    float acc[2][4][4];
    #pragma unroll
    for (int i = 0; i < 2; i++)
        #pragma unroll
        for (int j = 0; j < 4; j++)
            #pragma unroll
            for (int k = 0; k < 4; k++) acc[i][j][k] = 0.0f;

    #pragma unroll
    for (int s = 0; s < STAGES - 1; s++)
        if (s < nc) load_chunk(s, s);

    for (int c = 0; c < nc; c++) {
        if (c + 1 < nc) cp_wait<STAGES - 2>();
        else cp_wait<0>();
        __syncthreads();
        int nxt = c + STAGES - 1;
        if (nxt < nc) load_chunk(nxt, nxt % STAGES);

        int st = c % STAGES;
        uint32_t bufA = smb + (uint32_t)st * STAGE;
        uint32_t bufB = bufA + ABYTES;

        #pragma unroll
        for (int s = 0; s < 4; s++) {
            int kb = s * 32 + (lane >> 4) * 16;
            uint32_t aF[2][4], bF[2][4];
            #pragma unroll
            for (int fm = 0; fm < 2; fm++) {
                uint32_t off = (uint32_t)(wm * 32 + fm * 16 + (lane & 15)) * 128 + kb;
                ldmatrix_x4(aF[fm], bufA + (off ^ ((off >> 3) & 0x70)));
            }
            #pragma unroll
            for (int fb = 0; fb < 2; fb++) {
                uint32_t off = (uint32_t)(wn * 32 + fb * 16 + (lane & 15)) * 128 + kb;
                ldmatrix_x4(bF[fb], bufB + (off ^ ((off >> 3) & 0x70)));
            }
            #pragma unroll
            for (int fm = 0; fm < 2; fm++)
                #pragma unroll
                for (int fn = 0; fn < 4; fn++) {
                    int fb = fn >> 1, odd = fn & 1;
                    mma16816(acc[fm][fn], aF[fm], bF[fb][odd], bF[fb][odd + 2]);
                }
        }
    }

    // epilogue
    #pragma unroll
    for (int fm = 0; fm < 2; fm++) {
        #pragma unroll
        for (int fn = 0; fn < 4; fn++) {
            int gr = row0 + wm * 32 + fm * 16 + (lane >> 2);
            int gc = col0 + wn * 32 + fn * 8 + 2 * (lane & 3);
            float v0 = acc[fm][fn][0], v1 = acc[fm][fn][1];
            float v2 = acc[fm][fn][2], v3 = acc[fm][fn][3];
            if (MODE >= 1) {
                float b0 = bias[gc], b1 = bias[gc + 1];
                v0 += b0; v1 += b1; v2 += b0; v3 += b1;
            }
            if (MODE == 2) {
                v0 += resid[(long)gr * N + gc];
                v1 += resid[(long)gr * N + gc + 1];
                v2 += resid[(long)(gr + 8) * N + gc];
                v3 += resid[(long)(gr + 8) * N + gc + 1];
            }
            if (MODE == 3) {
                v0 = fmaxf(v0, 0.0f); v1 = fmaxf(v1, 0.0f);
                v2 = fmaxf(v2, 0.0f); v3 = fmaxf(v3, 0.0f);
            }
            *(float2*)&C[(long)gr * N + gc] = make_float2(v0, v1);
            *(float2*)&C[(long)(gr + 8) * N + gc] = make_float2(v2, v3);
        }
    }
}

static void run_tc(const __nv_bfloat16* A, const __nv_bfloat16* B, const float* bias,
                   const float* resid, float* C, int N, int K3, int mode) {
    dim3 grid(N / 128, BS_ / 64);
    if (mode == 0)      mma_gemm_kernel<0><<<grid, 256, SMEM_BM64>>>(A, B, bias, resid, C, N, K3);
    else if (mode == 1) mma_gemm_kernel<1><<<grid, 256, SMEM_BM64>>>(A, B, bias, resid, C, N, K3);
    else if (mode == 2) mma_gemm_kernel<2><<<grid, 256, SMEM_BM64>>>(A, B, bias, resid, C, N, K3);
    else                mma_gemm_kernel<3><<<grid, 256, SMEM_BM64>>>(A, B, bias, resid, C, N, K3);
}

// ---------------- embedding ----------------
__global__ void embed_kernel(const int* __restrict__ tokens,
                             const float* __restrict__ tok_emb,
                             const float* __restrict__ pos_emb,
                             float* __restrict__ h) {
    int i = blockIdx.x * blockDim.x + threadIdx.x;
    if (i >= BS_ * D_) return;
    int d = i % D_;
    int bs = i / D_;
    int s = bs % S_;
    int tok = tokens[bs];
    h[i] = tok_emb[(size_t)tok * D_ + d] + pos_emb[(size_t)s * D_ + d];
}

// ---------------- layernorm ----------------
__global__ void layernorm_kernel(const float* __restrict__ x,
                                 const float* __restrict__ g,
                                 const float* __restrict__ b,
                                 float* __restrict__ y) {
    int row = blockIdx.x;
    const float* xr = x + (size_t)row * D_;
    float* yr = y + (size_t)row * D_;
    float vals[4];
    float s = 0.0f;
    #pragma unroll
    for (int j = 0; j < 4; j++) { vals[j] = xr[threadIdx.x + j * 256]; s += vals[j]; }
    float mean = blockReduceSum(s) * (1.0f / D_);
    float var = 0.0f;
    #pragma unroll
    for (int j = 0; j < 4; j++) { float d = vals[j] - mean; var += d * d; }
    var = blockReduceSum(var) * (1.0f / D_);
    float rstd = rsqrtf(var + 1e-5f);
    #pragma unroll
    for (int j = 0; j < 4; j++) {
        int i = threadIdx.x + j * 256;
        yr[i] = (vals[j] - mean) * rstd * g[i] + b[i];
    }
}

// ---------------- flash-tiled causal attention ----------------
#define QT 64
#define ROWP 68
__global__ __launch_bounds__(256) void flash_attn_kernel(const float* __restrict__ QKV,
                                                         float* __restrict__ O) {
    extern __shared__ float fsm[];
    float* sQ = fsm;
    float* sK = fsm + 64 * ROWP;
    float* sV = fsm + 2 * 64 * ROWP;
    float* sP = fsm + 3 * 64 * ROWP;

    int qt = blockIdx.x, h = blockIdx.y, b = blockIdx.z;
    int q0 = qt * QT;
    int tid = threadIdx.x;
    int r = tid >> 2, c4 = tid & 3;
    const float scale = 0.03125f;  // D^-0.5 (reference scales by embedding dim)

    #pragma unroll
    for (int i = 0; i < 4; i++) {
        int lin = tid + i * 256;
        int rr = lin >> 4, cc = (lin & 15) * 4;
        float4 v = *(const float4*)&QKV[((size_t)(b * S_ + q0 + rr)) * K3D + h * DH_ + cc];
        *(float4*)&sQ[rr * ROWP + cc] = v;
    }

    float m_run = -1.0e30f, l_run = 0.0f;
    float acc[16];
    #pragma unroll
    for (int i = 0; i < 16; i++) acc[i] = 0.0f;

    for (int jt = 0; jt <= qt; jt++) {
        __syncthreads();
        int k0 = jt * QT;
        #pragma unroll
        for (int i = 0; i < 4; i++) {
            int lin = tid + i * 256;
            int rr = lin >> 4, cc = (lin & 15) * 4;
            size_t base = ((size_t)(b * S_ + k0 + rr)) * K3D + h * DH_ + cc;
            *(float4*)&sK[rr * ROWP + cc] = *(const float4*)&QKV[base + D_];
            *(float4*)&sV[rr * ROWP + cc] = *(const float4*)&QKV[base + 2 * D_];
        }
        __syncthreads();

        float sc[16];
        float tmax = -1.0e30f;
        bool diag = (jt == qt);
        #pragma unroll
        for (int kk = 0; kk < 16; kk++) {
            int kl = kk * 4 + c4;
            float s = 0.0f;
            const float* qr = &sQ[r * ROWP];
            const float* kr = &sK[kl * ROWP];
            #pragma unroll
            for (int e = 0; e < DH_; e++) s = fmaf(qr[e], kr[e], s);
            s *= scale;
            if (diag && kl > r) s = -1.0e30f;
            sc[kk] = s;
            tmax = fmaxf(tmax, s);
        }
        tmax = fmaxf(tmax, __shfl_xor_sync(0xffffffffu, tmax, 1));
        tmax = fmaxf(tmax, __shfl_xor_sync(0xffffffffu, tmax, 2));
        float m_new = fmaxf(m_run, tmax);
        float f = __expf(m_run - m_new);
        float sp = 0.0f;
        #pragma unroll
        for (int kk = 0; kk < 16; kk++) {
            float p = __expf(sc[kk] - m_new);
            sP[r * ROWP + kk * 4 + c4] = p;
            sp += p;
        }
        sp += __shfl_xor_sync(0xffffffffu, sp, 1);
        sp += __shfl_xor_sync(0xffffffffu, sp, 2);
        l_run = l_run * f + sp;
        m_run = m_new;
        #pragma unroll
        for (int i = 0; i < 16; i++) acc[i] *= f;
        __syncwarp();

        const float* pr = &sP[r * ROWP];
        #pragma unroll 8
        for (int kk = 0; kk < 64; kk++) {
            float p = pr[kk];
            const float* vr = &sV[kk * ROWP + c4 * 16];
            #pragma unroll
            for (int d = 0; d < 16; d++) acc[d] = fmaf(p, vr[d], acc[d]);
        }
    }

    float inv = 1.0f / l_run;
    size_t obase = ((size_t)(b * S_ + q0 + r)) * D_ + h * DH_ + c4 * 16;
    #pragma unroll
    for (int d = 0; d < 16; d += 4) {
        float4 v = make_float4(acc[d] * inv, acc[d + 1] * inv, acc[d + 2] * inv, acc[d + 3] * inv);
        *(float4*)&O[obase + d] = v;
    }
}
#define ATTN_SMEM (4 * 64 * ROWP * 4)

// ---------------- loss ----------------
__global__ void zero_kernel(float* p) { *p = 0.0f; }

__global__ void loss_kernel(const float* __restrict__ logits,
                            const int* __restrict__ targets,
                            float* __restrict__ loss, float invN) {
    int row = blockIdx.x;
    const float* lr = logits + (size_t)row * V_;
    float lmax = -3.0e38f;
    for (int i = threadIdx.x; i < V_; i += blockDim.x) lmax = fmaxf(lmax, lr[i]);
    float m = blockReduceMax(lmax);
    float lsum = 0.0f;
    for (int i = threadIdx.x; i < V_; i += blockDim.x) lsum += __expf(lr[i] - m);
    float s = blockReduceSum(lsum);
    if (threadIdx.x == 0) {
        float lse = m + logf(s);
        float nll = lse - lr[targets[row]];
        atomicAdd(loss, nll * invN);
    }
}

// ---------------- launch ----------------
extern "C" void kernel_launch(void* const* d_in, const int* in_sizes, int n_in,
                              void* d_out, int out_size) {
    const int* tokens = (const int*)d_in[0];
    const int* targets = (const int*)d_in[1];
    const float* tok_emb = (const float*)d_in[2];
    const float* pos_emb = (const float*)d_in[3];
    const float* Wq = (const float*)d_in[4];
    const float* Wk = (const float*)d_in[5];
    const float* Wv = (const float*)d_in[6];
    const float* Wo = (const float*)d_in[7];
    const float* bo = (const float*)d_in[8];
    const float* ln1_g = (const float*)d_in[9];
    const float* ln1_b = (const float*)d_in[10];
    const float* ln2_g = (const float*)d_in[11];
    const float* ln2_b = (const float*)d_in[12];
    const float* W1 = (const float*)d_in[13];
    const float* b1 = (const float*)d_in[14];
    const float* W2 = (const float*)d_in[15];
    const float* b2 = (const float*)d_in[16];
    const float* lnf_g = (const float*)d_in[17];
    const float* lnf_b = (const float*)d_in[18];
    const float* Wout = (const float*)d_in[19];
    const float* bout = (const float*)d_in[20];
    float* out = (float*)d_out;

    cudaFuncSetAttribute((const void*)mma_gemm_kernel<0>, cudaFuncAttributeMaxDynamicSharedMemorySize, SMEM_BM64);
    cudaFuncSetAttribute((const void*)mma_gemm_kernel<1>, cudaFuncAttributeMaxDynamicSharedMemorySize, SMEM_BM64);
    cudaFuncSetAttribute((const void*)mma_gemm_kernel<2>, cudaFuncAttributeMaxDynamicSharedMemorySize, SMEM_BM64);
    cudaFuncSetAttribute((const void*)mma_gemm_kernel<3>, cudaFuncAttributeMaxDynamicSharedMemorySize, SMEM_BM64);
    cudaFuncSetAttribute((const void*)flash_attn_kernel, cudaFuncAttributeMaxDynamicSharedMemorySize, ATTN_SMEM);

    float *h, *xn, *qkv, *o, *ff;
    __nv_bfloat16 *abig, *bqkv, *bwo, *bw1, *bw2, *bwout;
    cudaGetSymbolAddress((void**)&h, g_h);
    cudaGetSymbolAddress((void**)&xn, g_xn);
    cudaGetSymbolAddress((void**)&qkv, g_qkv);
    cudaGetSymbolAddress((void**)&o, g_o);
    cudaGetSymbolAddress((void**)&ff, g_ff);
    cudaGetSymbolAddress((void**)&abig, g_abig);
    cudaGetSymbolAddress((void**)&bqkv, g_bqkv);
    cudaGetSymbolAddress((void**)&bwo, g_bwo);
    cudaGetSymbolAddress((void**)&bw1, g_bw1);
    cudaGetSymbolAddress((void**)&bw2, g_bw2);
    cudaGetSymbolAddress((void**)&bwout, g_bwout);

    // ---- weight prep: transpose to [N,K] and bf16x3 split ----
    dim3 tb(32, 8);
    transpose_split_kernel<<<dim3(2, 32, L_ * H_), tb>>>(Wq, bqkv, D_, DH_, (long)D_ * DH_, (long)K3D * K3D, H_, 0, K3D);
    transpose_split_kernel<<<dim3(2, 32, L_ * H_), tb>>>(Wk, bqkv, D_, DH_, (long)D_ * DH_, (long)K3D * K3D, H_, D_, K3D);
    transpose_split_kernel<<<dim3(2, 32, L_ * H_), tb>>>(Wv, bqkv, D_, DH_, (long)D_ * DH_, (long)K3D * K3D, H_, 2 * D_, K3D);
    transpose_split_kernel<<<dim3(32, 32, L_), tb>>>(Wo, bwo, D_, D_, (long)D_ * D_, (long)D_ * K3D, 1, 0, K3D);
    transpose_split_kernel<<<dim3(128, 32, L_), tb>>>(W1, bw1, D_, FF_, (long)D_ * FF_, (long)FF_ * K3D, 1, 0, K3D);
    transpose_split_kernel<<<dim3(32, 128, L_), tb>>>(W2, bw2, FF_, D_, (long)FF_ * D_, (long)D_ * K3F, 1, 0, K3F);
    transpose_split_kernel<<<dim3(1000, 32, 1), tb>>>(Wout, bwout, D_, V_, 0, 0, 1, 0, K3D);

    embed_kernel<<<(BS_ * D_ + 255) / 256, 256>>>(tokens, tok_emb, pos_emb, h);

    for (int l = 0; l < L_; l++) {
        layernorm_kernel<<<BS_, 256>>>(h, ln1_g + (size_t)l * D_, ln1_b + (size_t)l * D_, xn);
        act_split_kernel<<<BS_ * D_ / 256, 256>>>(xn, abig, D_);
        run_tc(abig, bqkv + (size_t)l * K3D * K3D, nullptr, nullptr, qkv, K3D, K3D, 0);
        dim3 ag(S_ / QT, H_, B_);
        flash_attn_kernel<<<ag, 256, ATTN_SMEM>>>(qkv, o);
        act_split_kernel<<<BS_ * D_ / 256, 256>>>(o, abig, D_);
        run_tc(abig, bwo + (size_t)l * D_ * K3D, bo + (size_t)l * D_, h, h, D_, K3D, 2);
        layernorm_kernel<<<BS_, 256>>>(h, ln2_g + (size_t)l * D_, ln2_b + (size_t)l * D_, xn);
        act_split_kernel<<<BS_ * D_ / 256, 256>>>(xn, abig, D_);
        run_tc(abig, bw1 + (size_t)l * FF_ * K3D, b1 + (size_t)l * FF_, nullptr, ff, FF_, K3D, 3);
        act_split_kernel<<<BS_ * FF_ / 256, 256>>>(ff, abig, FF_);
        run_tc(abig, bw2 + (size_t)l * D_ * K3F, b2 + (size_t)l * D_, h, h, D_, K3F, 2);
    }

    layernorm_kernel<<<BS_, 256>>>(h, lnf_g, lnf_b, xn);
    act_split_kernel<<<BS_ * D_ / 256, 256>>>(xn, abig, D_);
    run_tc(abig, bwout, bout, nullptr, out, V_, K3D, 1);

    long long BSV = (long long)BS_ * V_;
    if ((long long)out_size > BSV) {
        zero_kernel<<<1, 1>>>(out + BSV);
        loss_kernel<<<BS_, 256>>>(out, targets, out + BSV, 1.0f / BS_);
    }
}

// round 9
// speedup vs baseline: 1.0591x; 1.0061x over previous
#include <cuda_runtime.h>
#include <cuda_bf16.h>
#include <cstdint>
#include <math.h>

// Problem constants
#define B_ 2
#define S_ 1024
#define D_ 1024
#define H_ 16
#define DH_ 64
#define L_ 8
#define FF_ 4096
#define V_ 32000
#define BS_ (B_ * S_)
#define K3D (3 * D_)    // 3072
#define K3F (3 * FF_)   // 12288

// ---------------- scratch (device globals) ----------------
__device__ float g_h[BS_ * D_];
__device__ float g_qkv[BS_ * K3D];
__device__ float g_o[BS_ * D_];
__device__ float g_ff[BS_ * FF_];
__device__ __nv_bfloat16 g_abig[BS_ * K3F];
__device__ __nv_bfloat16 g_bqkv[(size_t)L_ * K3D * K3D];
__device__ __nv_bfloat16 g_bwo[(size_t)L_ * D_ * K3D];
__device__ __nv_bfloat16 g_bw1[(size_t)L_ * FF_ * K3D];
__device__ __nv_bfloat16 g_bw2[(size_t)L_ * D_ * K3F];
__device__ __nv_bfloat16 g_bwout[(size_t)V_ * K3D];

// ---------------- helpers ----------------
__device__ __forceinline__ uint32_t smem_u32(const void* p) {
    uint32_t a;
    asm("{ .reg .u64 t; cvta.to.shared.u64 t, %1; cvt.u32.u64 %0, t; }" : "=r"(a) : "l"(p));
    return a;
}
__device__ __forceinline__ void cp_async16(uint32_t dst, const void* src) {
    asm volatile("cp.async.cg.shared.global [%0], [%1], 16;" :: "r"(dst), "l"(src) : "memory");
}
__device__ __forceinline__ void cp_commit() {
    asm volatile("cp.async.commit_group;" ::: "memory");
}
template <int N>
__device__ __forceinline__ void cp_wait() {
    asm volatile("cp.async.wait_group %0;" :: "n"(N) : "memory");
}
__device__ __forceinline__ void ldmatrix_x4(uint32_t* r, uint32_t addr) {
    asm volatile("ldmatrix.sync.aligned.m8n8.x4.shared.b16 {%0,%1,%2,%3}, [%4];"
                 : "=r"(r[0]), "=r"(r[1]), "=r"(r[2]), "=r"(r[3]) : "r"(addr));
}
__device__ __forceinline__ void mma16816(float* c, const uint32_t* a, uint32_t b0, uint32_t b1) {
    asm volatile(
        "mma.sync.aligned.m16n8k16.row.col.f32.bf16.bf16.f32 "
        "{%0,%1,%2,%3}, {%4,%5,%6,%7}, {%8,%9}, {%0,%1,%2,%3};"
        : "+f"(c[0]), "+f"(c[1]), "+f"(c[2]), "+f"(c[3])
        : "r"(a[0]), "r"(a[1]), "r"(a[2]), "r"(a[3]), "r"(b0), "r"(b1));
}

// ---------------- reductions ----------------
__device__ __forceinline__ float warpReduceSum(float v) {
    #pragma unroll
    for (int o = 16; o > 0; o >>= 1) v += __shfl_xor_sync(0xffffffffu, v, o);
    return v;
}
__device__ __forceinline__ float warpReduceMax(float v) {
    #pragma unroll
    for (int o = 16; o > 0; o >>= 1) v = fmaxf(v, __shfl_xor_sync(0xffffffffu, v, o));
    return v;
}
__device__ float blockReduceSum(float v) {
    __shared__ float sh[33];
    __syncthreads();
    int lane = threadIdx.x & 31, w = threadIdx.x >> 5;
    v = warpReduceSum(v);
    if (lane == 0) sh[w] = v;
    __syncthreads();
    int nw = (blockDim.x + 31) >> 5;
    float r = (threadIdx.x < nw) ? sh[threadIdx.x] : 0.0f;
    if (w == 0) { r = warpReduceSum(r); if (lane == 0) sh[32] = r; }
    __syncthreads();
    return sh[32];
}
__device__ float blockReduceMax(float v) {
    __shared__ float sh[33];
    __syncthreads();
    int lane = threadIdx.x & 31, w = threadIdx.x >> 5;
    v = warpReduceMax(v);
    if (lane == 0) sh[w] = v;
    __syncthreads();
    int nw = (blockDim.x + 31) >> 5;
    float r = (threadIdx.x < nw) ? sh[threadIdx.x] : -3.0e38f;
    if (w == 0) { r = warpReduceMax(r); if (lane == 0) sh[32] = r; }
    __syncthreads();
    return sh[32];
}

// ---------------- weight transpose + bf16x3 split -----------------
__global__ void transpose_split_kernel(const float* __restrict__ W, __nv_bfloat16* __restrict__ out,
                                       int K, int N, long in_z_stride, long out_l_stride,
                                       int h_group, int row_off, int Kp) {
    int z = blockIdx.z;
    int l = z / h_group, h = z % h_group;
    const float* Win = W + (long)z * in_z_stride;
    __nv_bfloat16* O = out + (long)l * out_l_stride;
    int base_row = row_off + h * N;
    __shared__ float t[32][33];
    int kb = blockIdx.y * 32, nb = blockIdx.x * 32;
    #pragma unroll
    for (int j = 0; j < 4; j++) {
        int r = threadIdx.y + j * 8;
        int k = kb + r, n = nb + threadIdx.x;
        t[r][threadIdx.x] = (k < K && n < N) ? Win[(long)k * N + n] : 0.0f;
    }
    __syncthreads();
    #pragma unroll
    for (int j = 0; j < 4; j++) {
        int r = threadIdx.y + j * 8;
        int n = nb + r, k = kb + threadIdx.x;
        if (n < N && k < K) {
            float w = t[threadIdx.x][r];
            __nv_bfloat16 hi = __float2bfloat16(w);
            __nv_bfloat16 lo = __float2bfloat16(w - __bfloat162float(hi));
            long ro = (long)(base_row + n) * Kp;
            O[ro + k] = hi;
            O[ro + K + k] = lo;
            O[ro + 2 * K + k] = hi;
        }
    }
}

// Activation split: A[M,K] fp32 -> [hi | hi | lo] bf16 [M, 3K]
__global__ void act_split_kernel(const float* __restrict__ A, __nv_bfloat16* __restrict__ out, int K) {
    long i = (long)blockIdx.x * 256 + threadIdx.x;
    int k = (int)(i % K);
    long m = i / K;
    float w = A[i];
    __nv_bfloat16 hi = __float2bfloat16(w);
    __nv_bfloat16 lo = __float2bfloat16(w - __bfloat162float(hi));
    long ro = m * (long)(3 * K);
    out[ro + k] = hi;
    out[ro + K + k] = hi;
    out[ro + 2 * K + k] = lo;
}

// ---------------- mma.sync GEMM: C[M,N] = A[M,K'] * B[N,K']^T ----------------
// BM=64: 256 thr, 8 warps 2(M)x4(N), warp tile 32x32, 2 CTAs/SM.
// BK=64, 3-stage cp.async pipeline. Grid: x = M blocks (fastest) for L2 B reuse.
// MODE: 0 none, 1 bias, 2 bias+resid, 3 bias+relu
#define STAGES 3
#define SMEM_BM64 (STAGES * (64 * 128 + 16384))
template <int MODE>
__global__ __launch_bounds__(256, 2) void mma_gemm_kernel(
    const __nv_bfloat16* __restrict__ A, const __nv_bfloat16* __restrict__ Bw,
    const float* __restrict__ bias, const float* __restrict__ resid,
    float* __restrict__ C, int N, int K3) {
    constexpr int ABYTES = 64 * 128;
    constexpr int STAGE = ABYTES + 16384;

    extern __shared__ char sm[];
    uint32_t smb = smem_u32(sm);

    int tid = threadIdx.x, lane = tid & 31, wid = tid >> 5;
    int wm = wid & 1;          // 2 warps along M
    int wn = wid >> 1;         // 4 warps along N
    int row0 = blockIdx.x * 64, col0 = blockIdx.y * 128;   // M on x: wave shares B cols

    const char* Ab = (const char*)A;
    const char* Bb = (const char*)Bw;
    long strideB = (long)K3 * 2;

    int nc = K3 >> 6;

    auto load_chunk = [&](int c, int s) {
        long kcb = (long)c * 128;
        uint32_t bA = smb + (uint32_t)s * STAGE;
        uint32_t bB = bA + ABYTES;
        #pragma unroll
        for (int j = 0; j < 2; j++) {
            int i = tid + j * 256;
            int r = i >> 3;
            uint32_t cb = (uint32_t)(i & 7) * 16;
            uint32_t off = (uint32_t)r * 128 + cb;
            uint32_t sw = off ^ ((off >> 3) & 0x70);
            cp_async16(bA + sw, Ab + (long)(row0 + r) * strideB + kcb + cb);
        }
        #pragma unroll
        for (int j = 0; j < 4; j++) {
            int i = tid + j * 256;
            int r = i >> 3;
            uint32_t cb = (uint32_t)(i & 7) * 16;
            uint32_t off = (uint32_t)r * 128 + cb;
            uint32_t sw = off ^ ((off >> 3) & 0x70);
            cp_async16(bB + sw, Bb + (long)(col0 + r) * strideB + kcb + cb);
        }
        cp_commit();
    };

    float acc[2][4][4];
    #pragma unroll
    for (int i = 0; i < 2; i++)
        #pragma unroll
        for (int j = 0; j < 4; j++)
            #pragma unroll
            for (int k = 0; k < 4; k++) acc[i][j][k] = 0.0f;

    #pragma unroll
    for (int s = 0; s < STAGES - 1; s++)
        if (s < nc) load_chunk(s, s);

    for (int c = 0; c < nc; c++) {
        if (c + 1 < nc) cp_wait<STAGES - 2>();
        else cp_wait<0>();
        __syncthreads();
        int nxt = c + STAGES - 1;
        if (nxt < nc) load_chunk(nxt, nxt % STAGES);

        int st = c % STAGES;
        uint32_t bufA = smb + (uint32_t)st * STAGE;
        uint32_t bufB = bufA + ABYTES;

        #pragma unroll
        for (int s = 0; s < 4; s++) {
            int kb = s * 32 + (lane >> 4) * 16;
            uint32_t aF[2][4], bF[2][4];
            #pragma unroll
            for (int fm = 0; fm < 2; fm++) {
                uint32_t off = (uint32_t)(wm * 32 + fm * 16 + (lane & 15)) * 128 + kb;
                ldmatrix_x4(aF[fm], bufA + (off ^ ((off >> 3) & 0x70)));
            }
            #pragma unroll
            for (int fb = 0; fb < 2; fb++) {
                uint32_t off = (uint32_t)(wn * 32 + fb * 16 + (lane & 15)) * 128 + kb;
                ldmatrix_x4(bF[fb], bufB + (off ^ ((off >> 3) & 0x70)));
            }
            #pragma unroll
            for (int fm = 0; fm < 2; fm++)
                #pragma unroll
                for (int fn = 0; fn < 4; fn++) {
                    int fb = fn >> 1, odd = fn & 1;
                    mma16816(acc[fm][fn], aF[fm], bF[fb][odd], bF[fb][odd + 2]);
                }
        }
    }

    // epilogue
    #pragma unroll
    for (int fm = 0; fm < 2; fm++) {
        #pragma unroll
        for (int fn = 0; fn < 4; fn++) {
            int gr = row0 + wm * 32 + fm * 16 + (lane >> 2);
            int gc = col0 + wn * 32 + fn * 8 + 2 * (lane & 3);
            float v0 = acc[fm][fn][0], v1 = acc[fm][fn][1];
            float v2 = acc[fm][fn][2], v3 = acc[fm][fn][3];
            if (MODE >= 1) {
                float b0 = bias[gc], b1 = bias[gc + 1];
                v0 += b0; v1 += b1; v2 += b0; v3 += b1;
            }
            if (MODE == 2) {
                v0 += resid[(long)gr * N + gc];
                v1 += resid[(long)gr * N + gc + 1];
                v2 += resid[(long)(gr + 8) * N + gc];
                v3 += resid[(long)(gr + 8) * N + gc + 1];
            }
            if (MODE == 3) {
                v0 = fmaxf(v0, 0.0f); v1 = fmaxf(v1, 0.0f);
                v2 = fmaxf(v2, 0.0f); v3 = fmaxf(v3, 0.0f);
            }
            *(float2*)&C[(long)gr * N + gc] = make_float2(v0, v1);
            *(float2*)&C[(long)(gr + 8) * N + gc] = make_float2(v2, v3);
        }
    }
}

static void run_tc(const __nv_bfloat16* A, const __nv_bfloat16* B, const float* bias,
                   const float* resid, float* C, int N, int K3, int mode) {
    dim3 grid(BS_ / 64, N / 128);   // M on x (fastest): concurrent CTAs share B columns
    if (mode == 0)      mma_gemm_kernel<0><<<grid, 256, SMEM_BM64>>>(A, B, bias, resid, C, N, K3);
    else if (mode == 1) mma_gemm_kernel<1><<<grid, 256, SMEM_BM64>>>(A, B, bias, resid, C, N, K3);
    else if (mode == 2) mma_gemm_kernel<2><<<grid, 256, SMEM_BM64>>>(A, B, bias, resid, C, N, K3);
    else                mma_gemm_kernel<3><<<grid, 256, SMEM_BM64>>>(A, B, bias, resid, C, N, K3);
}

// ---------------- embedding ----------------
__global__ void embed_kernel(const int* __restrict__ tokens,
                             const float* __restrict__ tok_emb,
                             const float* __restrict__ pos_emb,
                             float* __restrict__ h) {
    int i = blockIdx.x * blockDim.x + threadIdx.x;
    if (i >= BS_ * D_) return;
    int d = i % D_;
    int bs = i / D_;
    int s = bs % S_;
    int tok = tokens[bs];
    h[i] = tok_emb[(size_t)tok * D_ + d] + pos_emb[(size_t)s * D_ + d];
}

// ---------------- layernorm fused with bf16x3 split (coalesced writes) ------
__global__ void layernorm_split_kernel(const float* __restrict__ x,
                                       const float* __restrict__ g,
                                       const float* __restrict__ b,
                                       __nv_bfloat16* __restrict__ out) {
    int row = blockIdx.x;
    const float* xr = x + (size_t)row * D_;
    float vals[4];
    float s = 0.0f;
    #pragma unroll
    for (int j = 0; j < 4; j++) { vals[j] = xr[threadIdx.x + j * 256]; s += vals[j]; }
    float mean = blockReduceSum(s) * (1.0f / D_);
    float var = 0.0f;
    #pragma unroll
    for (int j = 0; j < 4; j++) { float d = vals[j] - mean; var += d * d; }
    var = blockReduceSum(var) * (1.0f / D_);
    float rstd = rsqrtf(var + 1e-5f);
    long ro = (long)row * K3D;
    #pragma unroll
    for (int j = 0; j < 4; j++) {
        int i = threadIdx.x + j * 256;
        float v = (vals[j] - mean) * rstd * g[i] + b[i];
        __nv_bfloat16 hi = __float2bfloat16(v);
        __nv_bfloat16 lo = __float2bfloat16(v - __bfloat162float(hi));
        out[ro + i] = hi;
        out[ro + D_ + i] = hi;
        out[ro + 2 * D_ + i] = lo;
    }
}

// ---------------- flash-tiled causal attention ----------------
#define QT 64
#define ROWP 68
__global__ __launch_bounds__(256) void flash_attn_kernel(const float* __restrict__ QKV,
                                                         float* __restrict__ O) {
    extern __shared__ float fsm[];
    float* sQ = fsm;
    float* sK = fsm + 64 * ROWP;
    float* sV = fsm + 2 * 64 * ROWP;
    float* sP = fsm + 3 * 64 * ROWP;

    int qt = blockIdx.x, h = blockIdx.y, b = blockIdx.z;
    int q0 = qt * QT;
    int tid = threadIdx.x;
    int r = tid >> 2, c4 = tid & 3;
    const float scale = 0.03125f;  // D^-0.5 (reference scales by embedding dim)

    #pragma unroll
    for (int i = 0; i < 4; i++) {
        int lin = tid + i * 256;
        int rr = lin >> 4, cc = (lin & 15) * 4;
        float4 v = *(const float4*)&QKV[((size_t)(b * S_ + q0 + rr)) * K3D + h * DH_ + cc];
        *(float4*)&sQ[rr * ROWP + cc] = v;
    }

    float m_run = -1.0e30f, l_run = 0.0f;
    float acc[16];
    #pragma unroll
    for (int i = 0; i < 16; i++) acc[i] = 0.0f;

    for (int jt = 0; jt <= qt; jt++) {
        __syncthreads();
        int k0 = jt * QT;
        #pragma unroll
        for (int i = 0; i < 4; i++) {
            int lin = tid + i * 256;
            int rr = lin >> 4, cc = (lin & 15) * 4;
            size_t base = ((size_t)(b * S_ + k0 + rr)) * K3D + h * DH_ + cc;
            *(float4*)&sK[rr * ROWP + cc] = *(const float4*)&QKV[base + D_];
            *(float4*)&sV[rr * ROWP + cc] = *(const float4*)&QKV[base + 2 * D_];
        }
        __syncthreads();

        float sc[16];
        float tmax = -1.0e30f;
        bool diag = (jt == qt);
        #pragma unroll
        for (int kk = 0; kk < 16; kk++) {
            int kl = kk * 4 + c4;
            float s = 0.0f;
            const float* qr = &sQ[r * ROWP];
            const float* kr = &sK[kl * ROWP];
            #pragma unroll
            for (int e = 0; e < DH_; e++) s = fmaf(qr[e], kr[e], s);
            s *= scale;
            if (diag && kl > r) s = -1.0e30f;
            sc[kk] = s;
            tmax = fmaxf(tmax, s);
        }
        tmax = fmaxf(tmax, __shfl_xor_sync(0xffffffffu, tmax, 1));
        tmax = fmaxf(tmax, __shfl_xor_sync(0xffffffffu, tmax, 2));
        float m_new = fmaxf(m_run, tmax);
        float f = __expf(m_run - m_new);
        float sp = 0.0f;
        #pragma unroll
        for (int kk = 0; kk < 16; kk++) {
            float p = __expf(sc[kk] - m_new);
            sP[r * ROWP + kk * 4 + c4] = p;
            sp += p;
        }
        sp += __shfl_xor_sync(0xffffffffu, sp, 1);
        sp += __shfl_xor_sync(0xffffffffu, sp, 2);
        l_run = l_run * f + sp;
        m_run = m_new;
        #pragma unroll
        for (int i = 0; i < 16; i++) acc[i] *= f;
        __syncwarp();

        const float* pr = &sP[r * ROWP];
        #pragma unroll 8
        for (int kk = 0; kk < 64; kk++) {
            float p = pr[kk];
            const float* vr = &sV[kk * ROWP + c4 * 16];
            #pragma unroll
            for (int d = 0; d < 16; d++) acc[d] = fmaf(p, vr[d], acc[d]);
        }
    }

    float inv = 1.0f / l_run;
    size_t obase = ((size_t)(b * S_ + q0 + r)) * D_ + h * DH_ + c4 * 16;
    #pragma unroll
    for (int d = 0; d < 16; d += 4) {
        float4 v = make_float4(acc[d] * inv, acc[d + 1] * inv, acc[d + 2] * inv, acc[d + 3] * inv);
        *(float4*)&O[obase + d] = v;
    }
}
#define ATTN_SMEM (4 * 64 * ROWP * 4)

// ---------------- loss ----------------
__global__ void zero_kernel(float* p) { *p = 0.0f; }

__global__ void loss_kernel(const float* __restrict__ logits,
                            const int* __restrict__ targets,
                            float* __restrict__ loss, float invN) {
    int row = blockIdx.x;
    const float* lr = logits + (size_t)row * V_;
    float lmax = -3.0e38f;
    for (int i = threadIdx.x; i < V_; i += blockDim.x) lmax = fmaxf(lmax, lr[i]);
    float m = blockReduceMax(lmax);
    float lsum = 0.0f;
    for (int i = threadIdx.x; i < V_; i += blockDim.x) lsum += __expf(lr[i] - m);
    float s = blockReduceSum(lsum);
    if (threadIdx.x == 0) {
        float lse = m + logf(s);
        float nll = lse - lr[targets[row]];
        atomicAdd(loss, nll * invN);
    }
}

// ---------------- launch ----------------
extern "C" void kernel_launch(void* const* d_in, const int* in_sizes, int n_in,
                              void* d_out, int out_size) {
    const int* tokens = (const int*)d_in[0];
    const int* targets = (const int*)d_in[1];
    const float* tok_emb = (const float*)d_in[2];
    const float* pos_emb = (const float*)d_in[3];
    const float* Wq = (const float*)d_in[4];
    const float* Wk = (const float*)d_in[5];
    const float* Wv = (const float*)d_in[6];
    const float* Wo = (const float*)d_in[7];
    const float* bo = (const float*)d_in[8];
    const float* ln1_g = (const float*)d_in[9];
    const float* ln1_b = (const float*)d_in[10];
    const float* ln2_g = (const float*)d_in[11];
    const float* ln2_b = (const float*)d_in[12];
    const float* W1 = (const float*)d_in[13];
    const float* b1 = (const float*)d_in[14];
    const float* W2 = (const float*)d_in[15];
    const float* b2 = (const float*)d_in[16];
    const float* lnf_g = (const float*)d_in[17];
    const float* lnf_b = (const float*)d_in[18];
    const float* Wout = (const float*)d_in[19];
    const float* bout = (const float*)d_in[20];
    float* out = (float*)d_out;

    cudaFuncSetAttribute((const void*)mma_gemm_kernel<0>, cudaFuncAttributeMaxDynamicSharedMemorySize, SMEM_BM64);
    cudaFuncSetAttribute((const void*)mma_gemm_kernel<1>, cudaFuncAttributeMaxDynamicSharedMemorySize, SMEM_BM64);
    cudaFuncSetAttribute((const void*)mma_gemm_kernel<2>, cudaFuncAttributeMaxDynamicSharedMemorySize, SMEM_BM64);
    cudaFuncSetAttribute((const void*)mma_gemm_kernel<3>, cudaFuncAttributeMaxDynamicSharedMemorySize, SMEM_BM64);
    cudaFuncSetAttribute((const void*)flash_attn_kernel, cudaFuncAttributeMaxDynamicSharedMemorySize, ATTN_SMEM);

    float *h, *qkv, *o, *ff;
    __nv_bfloat16 *abig, *bqkv, *bwo, *bw1, *bw2, *bwout;
    cudaGetSymbolAddress((void**)&h, g_h);
    cudaGetSymbolAddress((void**)&qkv, g_qkv);
    cudaGetSymbolAddress((void**)&o, g_o);
    cudaGetSymbolAddress((void**)&ff, g_ff);
    cudaGetSymbolAddress((void**)&abig, g_abig);
    cudaGetSymbolAddress((void**)&bqkv, g_bqkv);
    cudaGetSymbolAddress((void**)&bwo, g_bwo);
    cudaGetSymbolAddress((void**)&bw1, g_bw1);
    cudaGetSymbolAddress((void**)&bw2, g_bw2);
    cudaGetSymbolAddress((void**)&bwout, g_bwout);

    // ---- weight prep: transpose to [N,K] and bf16x3 split ----
    dim3 tb(32, 8);
    transpose_split_kernel<<<dim3(2, 32, L_ * H_), tb>>>(Wq, bqkv, D_, DH_, (long)D_ * DH_, (long)K3D * K3D, H_, 0, K3D);
    transpose_split_kernel<<<dim3(2, 32, L_ * H_), tb>>>(Wk, bqkv, D_, DH_, (long)D_ * DH_, (long)K3D * K3D, H_, D_, K3D);
    transpose_split_kernel<<<dim3(2, 32, L_ * H_), tb>>>(Wv, bqkv, D_, DH_, (long)D_ * DH_, (long)K3D * K3D, H_, 2 * D_, K3D);
    transpose_split_kernel<<<dim3(32, 32, L_), tb>>>(Wo, bwo, D_, D_, (long)D_ * D_, (long)D_ * K3D, 1, 0, K3D);
    transpose_split_kernel<<<dim3(128, 32, L_), tb>>>(W1, bw1, D_, FF_, (long)D_ * FF_, (long)FF_ * K3D, 1, 0, K3D);
    transpose_split_kernel<<<dim3(32, 128, L_), tb>>>(W2, bw2, FF_, D_, (long)FF_ * D_, (long)D_ * K3F, 1, 0, K3F);
    transpose_split_kernel<<<dim3(1000, 32, 1), tb>>>(Wout, bwout, D_, V_, 0, 0, 1, 0, K3D);

    embed_kernel<<<(BS_ * D_ + 255) / 256, 256>>>(tokens, tok_emb, pos_emb, h);

    for (int l = 0; l < L_; l++) {
        layernorm_split_kernel<<<BS_, 256>>>(h, ln1_g + (size_t)l * D_, ln1_b + (size_t)l * D_, abig);
        run_tc(abig, bqkv + (size_t)l * K3D * K3D, nullptr, nullptr, qkv, K3D, K3D, 0);
        dim3 ag(S_ / QT, H_, B_);
        flash_attn_kernel<<<ag, 256, ATTN_SMEM>>>(qkv, o);
        act_split_kernel<<<BS_ * D_ / 256, 256>>>(o, abig, D_);
        run_tc(abig, bwo + (size_t)l * D_ * K3D, bo + (size_t)l * D_, h, h, D_, K3D, 2);
        layernorm_split_kernel<<<BS_, 256>>>(h, ln2_g + (size_t)l * D_, ln2_b + (size_t)l * D_, abig);
        run_tc(abig, bw1 + (size_t)l * FF_ * K3D, b1 + (size_t)l * FF_, nullptr, ff, FF_, K3D, 3);
        act_split_kernel<<<BS_ * FF_ / 256, 256>>>(ff, abig, FF_);
        run_tc(abig, bw2 + (size_t)l * D_ * K3F, b2 + (size_t)l * D_, h, h, D_, K3F, 2);
    }

    layernorm_split_kernel<<<BS_, 256>>>(h, lnf_g, lnf_b, abig);
    run_tc(abig, bwout, bout, nullptr, out, V_, K3D, 1);

    long long BSV = (long long)BS_ * V_;
    if ((long long)out_size > BSV) {
        zero_kernel<<<1, 1>>>(out + BSV);
        loss_kernel<<<BS_, 256>>>(out, targets, out + BSV, 1.0f / BS_);
    }
}